// round 1
// baseline (speedup 1.0000x reference)
#include <cuda_runtime.h>

#define TILE_W 128
#define TILE_H 16
#define SM_W   (TILE_W + 2)   // 130
#define SM_H   (TILE_H + 2)   // 18
#define NTHREADS 256

__global__ __launch_bounds__(NTHREADS)
void conv3x3_kernel(const float* __restrict__ X,
                    const float* __restrict__ Kp,
                    float* __restrict__ O,
                    int H, int W)
{
    __shared__ float S[SM_H][SM_W];

    const int bc = blockIdx.z;                 // which (b, c) plane
    const int x0 = blockIdx.x * TILE_W;
    const int y0 = blockIdx.y * TILE_H;

    const float* __restrict__ Xp = X + (size_t)bc * H * W;
    float* __restrict__ Op       = O + (size_t)bc * H * W;

    // 3x3 kernel into registers (tiny; L1/L2 broadcast)
    const float k00 = __ldg(&Kp[0]), k01 = __ldg(&Kp[1]), k02 = __ldg(&Kp[2]);
    const float k10 = __ldg(&Kp[3]), k11 = __ldg(&Kp[4]), k12 = __ldg(&Kp[5]);
    const float k20 = __ldg(&Kp[6]), k21 = __ldg(&Kp[7]), k22 = __ldg(&Kp[8]);

    const int tid = threadIdx.x;

    // Cooperative halo load: rows [y0-1, y0+TILE_H], cols [x0-1, x0+TILE_W]
    #pragma unroll
    for (int i = tid; i < SM_H * SM_W; i += NTHREADS) {
        const int r  = i / SM_W;
        const int c  = i - r * SM_W;
        const int gy = y0 + r - 1;
        const int gx = x0 + c - 1;
        float v = 0.0f;
        if (gy >= 0 && gy < H && gx >= 0 && gx < W)
            v = Xp[(size_t)gy * W + gx];
        S[r][c] = v;
    }
    __syncthreads();

    // 256 threads cover 128 columns x 2 row-groups; each thread does 8 rows.
    const int tx  = tid & (TILE_W - 1);        // 0..127
    const int tyb = (tid >> 7) * 8;            // 0 or 8

    #pragma unroll
    for (int ry = 0; ry < 8; ry++) {
        const int r = tyb + ry;                // output row within tile, 0..15
        float s;
        s  = S[r    ][tx    ] * k00;
        s += S[r    ][tx + 1] * k01;
        s += S[r    ][tx + 2] * k02;
        s += S[r + 1][tx    ] * k10;
        s += S[r + 1][tx + 1] * k11;
        s += S[r + 1][tx + 2] * k12;
        s += S[r + 2][tx    ] * k20;
        s += S[r + 2][tx + 1] * k21;
        s += S[r + 2][tx + 2] * k22;
        Op[(size_t)(y0 + r) * W + (x0 + tx)] = s;
    }
}

extern "C" void kernel_launch(void* const* d_in, const int* in_sizes, int n_in,
                              void* d_out, int out_size)
{
    const float* X = (const float*)d_in[0];   // (16, 64, 256, 256) fp32
    const float* K = (const float*)d_in[1];   // (3, 3) fp32
    float* O = (float*)d_out;

    const int H = 256, W = 256;
    const int planes = in_sizes[0] / (H * W); // 16*64 = 1024

    dim3 block(NTHREADS, 1, 1);
    dim3 grid(W / TILE_W, H / TILE_H, planes); // (2, 16, 1024)
    conv3x3_kernel<<<grid, block>>>(X, K, O, H, W);
}

// round 2
// speedup vs baseline: 1.2369x; 1.2369x over previous
#include <cuda_runtime.h>

#define TILE_W 128
#define TILE_H 32
#define W4 (TILE_W / 4)        // 32 float4 per tile row
#define SROWS (TILE_H + 2)     // 34 input rows incl. halo
#define NTHREADS 256

__global__ __launch_bounds__(NTHREADS)
void conv3x3_v2(const float* __restrict__ X,
                const float* __restrict__ Kp,
                float* __restrict__ O,
                int H, int W)
{
    __shared__ float4 S4[SROWS][W4];   // interior (128 cols) as float4
    __shared__ float  SL[SROWS];       // left halo col (x0-1)
    __shared__ float  SR[SROWS];       // right halo col (x0+128)

    const int bc = blockIdx.z;
    const int x0 = blockIdx.x * TILE_W;
    const int y0 = blockIdx.y * TILE_H;

    const float* __restrict__ Xp = X + (size_t)bc * H * W;
    float* __restrict__ Op       = O + (size_t)bc * H * W;

    // 3x3 kernel -> registers
    const float k00 = __ldg(&Kp[0]), k01 = __ldg(&Kp[1]), k02 = __ldg(&Kp[2]);
    const float k10 = __ldg(&Kp[3]), k11 = __ldg(&Kp[4]), k12 = __ldg(&Kp[5]);
    const float k20 = __ldg(&Kp[6]), k21 = __ldg(&Kp[7]), k22 = __ldg(&Kp[8]);
    const float ka[3] = {k00, k10, k20};
    const float kb[3] = {k01, k11, k21};
    const float kc[3] = {k02, k12, k22};

    const int tid = threadIdx.x;
    const int W4g = W >> 2;            // 64 float4 per global row
    const int x04 = x0 >> 2;

    // ---- cooperative load: interior as float4 (34*32 = 1088 vec loads) ----
    const float4* __restrict__ Xp4 = (const float4*)Xp;
    #pragma unroll
    for (int i = tid; i < SROWS * W4; i += NTHREADS) {
        const int r  = i >> 5;         // /W4
        const int c  = i & (W4 - 1);
        const int gy = y0 + r - 1;
        float4 v = make_float4(0.f, 0.f, 0.f, 0.f);
        if (gy >= 0 && gy < H)
            v = Xp4[(size_t)gy * W4g + x04 + c];
        S4[r][c] = v;
    }
    // ---- halo columns (scalar) ----
    for (int i = tid; i < SROWS * 2; i += NTHREADS) {
        const int r    = i >> 1;
        const int side = i & 1;
        const int gy   = y0 + r - 1;
        const int gx   = side ? (x0 + TILE_W) : (x0 - 1);
        float v = 0.f;
        if (gy >= 0 && gy < H && gx >= 0 && gx < W)
            v = Xp[(size_t)gy * W + gx];
        if (side) SR[r] = v; else SL[r] = v;
    }
    __syncthreads();

    // ---- compute: warp = 128-wide x 4-row strip, rolling input rows ----
    const int warp = tid >> 5;
    const int lane = tid & 31;
    const int r0   = warp * 4;         // first output row of this warp (0..28)

    float4 acc0 = make_float4(0.f,0.f,0.f,0.f);
    float4 acc1 = acc0, acc2 = acc0, acc3 = acc0;

    #pragma unroll
    for (int j = 0; j < 6; j++) {      // input rows r0-1 .. r0+4 (smem rows r0+j)
        const int sr = r0 + j;
        const float4 v = S4[sr][lane];
        const float up = __shfl_up_sync(0xffffffffu, v.w, 1);
        const float dn = __shfl_down_sync(0xffffffffu, v.x, 1);
        const float lm1 = (lane == 0)  ? SL[sr] : up;
        const float rp1 = (lane == 31) ? SR[sr] : dn;

        #pragma unroll
        for (int o = 0; o < 4; o++) {
            const int kr = j - o;      // kernel row this input row plays for output o
            if (kr >= 0 && kr <= 2) {
                const float a = ka[kr], b = kb[kr], c = kc[kr];
                float4* accp = (o == 0) ? &acc0 : (o == 1) ? &acc1 : (o == 2) ? &acc2 : &acc3;
                accp->x += a * lm1 + b * v.x + c * v.y;
                accp->y += a * v.x + b * v.y + c * v.z;
                accp->z += a * v.y + b * v.z + c * v.w;
                accp->w += a * v.z + b * v.w + c * rp1;
            }
        }
    }

    // ---- vectorized stores ----
    float4* __restrict__ Op4 = (float4*)Op;
    const size_t base = (size_t)(y0 + r0) * W4g + x04 + lane;
    Op4[base            ] = acc0;
    Op4[base +     W4g  ] = acc1;
    Op4[base + 2 * W4g  ] = acc2;
    Op4[base + 3 * W4g  ] = acc3;
}

extern "C" void kernel_launch(void* const* d_in, const int* in_sizes, int n_in,
                              void* d_out, int out_size)
{
    const float* X = (const float*)d_in[0];   // (16, 64, 256, 256) fp32
    const float* K = (const float*)d_in[1];   // (3, 3) fp32
    float* O = (float*)d_out;

    const int H = 256, W = 256;
    const int planes = in_sizes[0] / (H * W); // 1024

    dim3 block(NTHREADS, 1, 1);
    dim3 grid(W / TILE_W, H / TILE_H, planes); // (2, 8, 1024)
    conv3x3_v2<<<grid, block>>>(X, K, O, H, W);
}

// round 4
// speedup vs baseline: 1.2691x; 1.0260x over previous
#include <cuda_runtime.h>

#define STRIP_W 128
#define STRIP_R 32            // output rows per warp
#define NTHREADS 256          // 8 warps * 32 rows = 256 rows = full plane height

__global__ __launch_bounds__(NTHREADS)
void conv3x3_v4(const float* __restrict__ X,
                const float* __restrict__ Kp,
                float* __restrict__ O,
                int H, int W)
{
    const int bc = blockIdx.z;
    const int x0 = blockIdx.x * STRIP_W;

    const float* __restrict__ Xp = X + (size_t)bc * H * W;
    float* __restrict__ Op       = O + (size_t)bc * H * W;

    const float k00 = __ldg(&Kp[0]), k01 = __ldg(&Kp[1]), k02 = __ldg(&Kp[2]);
    const float k10 = __ldg(&Kp[3]), k11 = __ldg(&Kp[4]), k12 = __ldg(&Kp[5]);
    const float k20 = __ldg(&Kp[6]), k21 = __ldg(&Kp[7]), k22 = __ldg(&Kp[8]);

    const int tid  = threadIdx.x;
    const int warp = tid >> 5;
    const int lane = tid & 31;
    const int y0   = warp * STRIP_R;

    const int W4g   = W >> 2;                 // 64
    const int base4 = (x0 >> 2) + lane;
    const float4* __restrict__ Xp4 = (const float4*)Xp;
    float4* __restrict__ Op4       = (float4*)Op;

    // Edge-lane halo vectors: lane 0 loads the float4 just left of the strip,
    // lane 31 the float4 just right. Predicated LDG (legal), values selected later.
    const bool do_l = (lane == 0)  && (x0 > 0);
    const bool do_r = (lane == 31) && (x0 + STRIP_W < W);

    const float4 Z = make_float4(0.f, 0.f, 0.f, 0.f);

    float4 v, vl, vr;

    // initial row: t = y0 - 1
    {
        const int t = y0 - 1;
        v = Z; vl = Z; vr = Z;
        if (t >= 0 && t < H) {
            v = Xp4[(size_t)t * W4g + base4];
            if (do_l) vl = Xp4[(size_t)t * W4g + base4 - 1];
            if (do_r) vr = Xp4[(size_t)t * W4g + base4 + 1];
        }
    }

    float4 accP = Z;   // out row t-1 (awaiting kernel row 2)
    float4 accQ = Z;   // out row t+1 partial (kernel row 0)

    #pragma unroll 4
    for (int i = 0; i <= STRIP_R + 1; i++) {
        const int t = y0 - 1 + i;

        // prefetch next input row
        float4 vn = Z, vln = Z, vrn = Z;
        const int tn = t + 1;
        if (i <= STRIP_R && tn >= 0 && tn < H) {
            vn = Xp4[(size_t)tn * W4g + base4];
            if (do_l) vln = Xp4[(size_t)tn * W4g + base4 - 1];
            if (do_r) vrn = Xp4[(size_t)tn * W4g + base4 + 1];
        }

        // horizontal neighbors: unconditional shuffles, then value selects
        const float up = __shfl_up_sync(0xffffffffu,   v.w, 1);
        const float dn = __shfl_down_sync(0xffffffffu, v.x, 1);
        const float L  = (lane == 0)  ? vl.w : up;   // 0 at image edge (vl = Z)
        const float R  = (lane == 31) ? vr.x : dn;

        // out row t-1 completes with kernel row 2 of input row t
        accP.x += k20 * L   + k21 * v.x + k22 * v.y;
        accP.y += k20 * v.x + k21 * v.y + k22 * v.z;
        accP.z += k20 * v.y + k21 * v.z + k22 * v.w;
        accP.w += k20 * v.z + k21 * v.w + k22 * R;
        if (i >= 2)
            Op4[(size_t)(t - 1) * W4g + base4] = accP;

        // out row t: previous partial + kernel row 1
        accP.x = accQ.x + (k10 * L   + k11 * v.x + k12 * v.y);
        accP.y = accQ.y + (k10 * v.x + k11 * v.y + k12 * v.z);
        accP.z = accQ.z + (k10 * v.y + k11 * v.z + k12 * v.w);
        accP.w = accQ.w + (k10 * v.z + k11 * v.w + k12 * R);

        // out row t+1: kernel row 0
        accQ.x = k00 * L   + k01 * v.x + k02 * v.y;
        accQ.y = k00 * v.x + k01 * v.y + k02 * v.z;
        accQ.z = k00 * v.y + k01 * v.z + k02 * v.w;
        accQ.w = k00 * v.z + k01 * v.w + k02 * R;

        v = vn; vl = vln; vr = vrn;
    }
}

extern "C" void kernel_launch(void* const* d_in, const int* in_sizes, int n_in,
                              void* d_out, int out_size)
{
    const float* X = (const float*)d_in[0];   // (16, 64, 256, 256) fp32
    const float* K = (const float*)d_in[1];   // (3, 3) fp32
    float* O = (float*)d_out;

    const int H = 256, W = 256;
    const int planes = in_sizes[0] / (H * W); // 1024

    dim3 block(NTHREADS, 1, 1);
    dim3 grid(W / STRIP_W, 1, planes);        // (2, 1, 1024)
    conv3x3_v4<<<grid, block>>>(X, K, O, H, W);
}